// round 1
// baseline (speedup 1.0000x reference)
#include <cuda_runtime.h>
#include <cstddef>

#define B_    8
#define L_    4096
#define C_    1024
#define D_    1024
#define N_    256
#define MLP_  512
#define TIT_  6

// ---------------- scratch (device globals; no allocation allowed) ----------
__device__ float g_xn  [(size_t)B_ * L_ * C_];
__device__ float g_k   [(size_t)B_ * L_ * D_];
__device__ float g_v   [(size_t)B_ * L_ * D_];
__device__ float g_attn[(size_t)B_ * L_ * N_];
__device__ float g_tmpl[B_ * N_ * D_];
__device__ float g_t   [B_ * N_ * D_];
__device__ float g_q   [B_ * N_ * D_];
__device__ float g_m   [B_ * N_ * D_];
__device__ float g_h   [B_ * N_ * MLP_];
__device__ float g_cs  [B_ * N_];

// ---------------- generic register-blocked SGEMM ---------------------------
// C[M,N] = alpha * A?B (+bias[n]) (relu) (+resid)
// TA==0: A is [M,K] row-major (lda=K-ish).  TA==1: A is [K,M] (lda = row len).
// TB==0: B is [K,N].                        TB==1: B is [N,K].
template<int TA, int TB, int BIAS, int RELU, int RESID>
__global__ void __launch_bounds__(256) sgemm(
    const float* __restrict__ A, const float* __restrict__ Bm,
    const float* __restrict__ bias, const float* __restrict__ Rm,
    float* __restrict__ Cm,
    int M, int N, int K, int lda, int ldb, int ldc,
    long long sA, long long sB, long long sC, float alpha)
{
    __shared__ float As[16][128];
    __shared__ float Bs[16][128];
    const int bz = blockIdx.z;
    A  += bz * sA;
    Bm += bz * sB;
    Cm += bz * sC;
    const float* Rp = Rm ? (Rm + bz * sC) : nullptr;
    const int m0 = blockIdx.y * 128;
    const int n0 = blockIdx.x * 128;
    const int tid = threadIdx.x;

    float acc[8][8];
#pragma unroll
    for (int i = 0; i < 8; i++)
#pragma unroll
        for (int j = 0; j < 8; j++) acc[i][j] = 0.f;

    for (int k0 = 0; k0 < K; k0 += 16) {
#pragma unroll
        for (int it = 0; it < 2; it++) {
            const int f = tid + it * 256;
            if (TA == 0) {
                const int row = f >> 2, kc = (f & 3) << 2;
                const float4 v4 = *(const float4*)(A + (size_t)(m0 + row) * lda + (k0 + kc));
                As[kc + 0][row] = v4.x; As[kc + 1][row] = v4.y;
                As[kc + 2][row] = v4.z; As[kc + 3][row] = v4.w;
            } else {
                const int kk = f >> 5, mc = (f & 31) << 2;
                *(float4*)&As[kk][mc] =
                    *(const float4*)(A + (size_t)(k0 + kk) * lda + (m0 + mc));
            }
            if (TB == 0) {
                const int kk = f >> 5, nc = (f & 31) << 2;
                *(float4*)&Bs[kk][nc] =
                    *(const float4*)(Bm + (size_t)(k0 + kk) * ldb + (n0 + nc));
            } else {
                const int row = f >> 2, kc = (f & 3) << 2;
                const float4 v4 = *(const float4*)(Bm + (size_t)(n0 + row) * ldb + (k0 + kc));
                Bs[kc + 0][row] = v4.x; Bs[kc + 1][row] = v4.y;
                Bs[kc + 2][row] = v4.z; Bs[kc + 3][row] = v4.w;
            }
        }
        __syncthreads();

        const int tx = tid & 15, ty = tid >> 4;
#pragma unroll
        for (int kk = 0; kk < 16; kk++) {
            float a[8], bb[8];
            *(float4*)&a[0]  = *(float4*)&As[kk][ty * 8];
            *(float4*)&a[4]  = *(float4*)&As[kk][ty * 8 + 4];
            *(float4*)&bb[0] = *(float4*)&Bs[kk][tx * 8];
            *(float4*)&bb[4] = *(float4*)&Bs[kk][tx * 8 + 4];
#pragma unroll
            for (int i = 0; i < 8; i++)
#pragma unroll
                for (int j = 0; j < 8; j++)
                    acc[i][j] = fmaf(a[i], bb[j], acc[i][j]);
        }
        __syncthreads();
    }

    const int tx = tid & 15, ty = tid >> 4;
#pragma unroll
    for (int i = 0; i < 8; i++) {
        const int m = m0 + ty * 8 + i;
#pragma unroll
        for (int j = 0; j < 8; j += 4) {
            const int n = n0 + tx * 8 + j;
            float4 r;
            r.x = acc[i][j + 0] * alpha; r.y = acc[i][j + 1] * alpha;
            r.z = acc[i][j + 2] * alpha; r.w = acc[i][j + 3] * alpha;
            if (BIAS) {
                const float4 bv = *(const float4*)(bias + n);
                r.x += bv.x; r.y += bv.y; r.z += bv.z; r.w += bv.w;
            }
            if (RELU) {
                r.x = fmaxf(r.x, 0.f); r.y = fmaxf(r.y, 0.f);
                r.z = fmaxf(r.z, 0.f); r.w = fmaxf(r.w, 0.f);
            }
            if (RESID) {
                const float4 rv = *(const float4*)(Rp + (size_t)m * ldc + n);
                r.x += rv.x; r.y += rv.y; r.z += rv.z; r.w += rv.w;
            }
            *(float4*)(Cm + (size_t)m * ldc + n) = r;
        }
    }
}

// ---------------- LayerNorm over 1024-wide rows ----------------------------
__global__ void __launch_bounds__(256) ln1024(
    const float* __restrict__ in, const float* __restrict__ g,
    const float* __restrict__ b, float* __restrict__ out)
{
    __shared__ float sh[8];
    __shared__ float s_mean, s_rstd;
    const size_t row = blockIdx.x;
    const int t = threadIdx.x;
    const float4 v = ((const float4*)(in + row * 1024))[t];

    float s = v.x + v.y + v.z + v.w;
#pragma unroll
    for (int o = 16; o; o >>= 1) s += __shfl_xor_sync(0xffffffffu, s, o);
    if ((t & 31) == 0) sh[t >> 5] = s;
    __syncthreads();
    if (t == 0) {
        float tt = 0.f;
#pragma unroll
        for (int i = 0; i < 8; i++) tt += sh[i];
        s_mean = tt * (1.f / 1024.f);
    }
    __syncthreads();
    const float mean = s_mean;
    const float dx = v.x - mean, dy = v.y - mean, dz = v.z - mean, dw = v.w - mean;

    float q = dx * dx + dy * dy + dz * dz + dw * dw;
#pragma unroll
    for (int o = 16; o; o >>= 1) q += __shfl_xor_sync(0xffffffffu, q, o);
    __syncthreads();
    if ((t & 31) == 0) sh[t >> 5] = q;
    __syncthreads();
    if (t == 0) {
        float tt = 0.f;
#pragma unroll
        for (int i = 0; i < 8; i++) tt += sh[i];
        s_rstd = rsqrtf(tt * (1.f / 1024.f) + 1e-5f);
    }
    __syncthreads();
    const float rstd = s_rstd;

    const float4 gv = ((const float4*)g)[t];
    const float4 bv = ((const float4*)b)[t];
    float4 o;
    o.x = dx * rstd * gv.x + bv.x;
    o.y = dy * rstd * gv.y + bv.y;
    o.z = dz * rstd * gv.z + bv.z;
    o.w = dw * rstd * gv.w + bv.w;
    ((float4*)(out + row * 1024))[t] = o;
}

// ---------------- softmax over N=256 + column-sum accumulation -------------
__global__ void __launch_bounds__(256) softmax_colsum(
    float* __restrict__ attn, float* __restrict__ colsum)
{
    __shared__ float sh[8];
    __shared__ float s_b;
    const size_t row = blockIdx.x;
    const int n = threadIdx.x;
    const float v = attn[row * 256 + n];

    float m = v;
#pragma unroll
    for (int o = 16; o; o >>= 1) m = fmaxf(m, __shfl_xor_sync(0xffffffffu, m, o));
    if ((n & 31) == 0) sh[n >> 5] = m;
    __syncthreads();
    if (n == 0) {
        float t = sh[0];
#pragma unroll
        for (int i = 1; i < 8; i++) t = fmaxf(t, sh[i]);
        s_b = t;
    }
    __syncthreads();
    const float e = __expf(v - s_b);
    __syncthreads();

    float s = e;
#pragma unroll
    for (int o = 16; o; o >>= 1) s += __shfl_xor_sync(0xffffffffu, s, o);
    if ((n & 31) == 0) sh[n >> 5] = s;
    __syncthreads();
    if (n == 0) {
        float t = 0.f;
#pragma unroll
        for (int i = 0; i < 8; i++) t += sh[i];
        s_b = t;
    }
    __syncthreads();
    const float a = e / s_b + 1e-8f;
    attn[row * 256 + n] = a;
    atomicAdd(&colsum[(row >> 12) * 256 + n], a);
}

__global__ void renorm_div(float* __restrict__ attn, const float* __restrict__ colsum)
{
    const size_t row = blockIdx.x;
    const int n = threadIdx.x;
    attn[row * 256 + n] /= colsum[(row >> 12) * 256 + n];
}

__global__ void zero_colsum(float* __restrict__ p)
{
    p[blockIdx.x * 256 + threadIdx.x] = 0.f;
}

// ---------------- tiled transpose: per batch [R,Cc] -> [Cc,R] --------------
__global__ void transpose_k(const float* __restrict__ in, float* __restrict__ out,
                            int R, int Cc)
{
    __shared__ float tile[32][33];
    const size_t base = (size_t)blockIdx.z * R * Cc;
    const int c0 = blockIdx.x * 32, r0 = blockIdx.y * 32;
#pragma unroll
    for (int i = threadIdx.y; i < 32; i += 8)
        tile[i][threadIdx.x] = in[base + (size_t)(r0 + i) * Cc + c0 + threadIdx.x];
    __syncthreads();
#pragma unroll
    for (int i = threadIdx.y; i < 32; i += 8)
        out[base + (size_t)(c0 + i) * R + r0 + threadIdx.x] = tile[threadIdx.x][i];
}

__global__ void bcast_tmpl(const float* __restrict__ tinit, float* __restrict__ tmpl)
{
    const size_t i = (size_t)blockIdx.x * 256 + threadIdx.x;
    tmpl[i] = tinit[i & ((size_t)N_ * D_ - 1)];
}

// ---------------- host orchestration ---------------------------------------
extern "C" void kernel_launch(void* const* d_in, const int* in_sizes, int n_in,
                              void* d_out, int out_size)
{
    const float* x       = (const float*)d_in[0];
    const float* tinit   = (const float*)d_in[1];
    const float* Wq      = (const float*)d_in[2];
    const float* Wk      = (const float*)d_in[3];
    const float* Wv      = (const float*)d_in[4];
    const float* ln_in_g = (const float*)d_in[5];
    const float* ln_in_b = (const float*)d_in[6];
    const float* ln_t_g  = (const float*)d_in[7];
    const float* ln_t_b  = (const float*)d_in[8];
    const float* ln_m_g  = (const float*)d_in[9];
    const float* ln_m_b  = (const float*)d_in[10];
    const float* W1      = (const float*)d_in[11];
    const float* b1      = (const float*)d_in[12];
    const float* W2      = (const float*)d_in[13];
    const float* b2      = (const float*)d_in[14];
    float* out = (float*)d_out;

    float *xn, *kb, *vb, *attn, *tmpl, *tb, *qb, *mb, *hb, *cs;
    cudaGetSymbolAddress((void**)&xn,   g_xn);
    cudaGetSymbolAddress((void**)&kb,   g_k);
    cudaGetSymbolAddress((void**)&vb,   g_v);
    cudaGetSymbolAddress((void**)&attn, g_attn);
    cudaGetSymbolAddress((void**)&tmpl, g_tmpl);
    cudaGetSymbolAddress((void**)&tb,   g_t);
    cudaGetSymbolAddress((void**)&qb,   g_q);
    cudaGetSymbolAddress((void**)&mb,   g_m);
    cudaGetSymbolAddress((void**)&hb,   g_h);
    cudaGetSymbolAddress((void**)&cs,   g_cs);

    const dim3 tblk(32, 8);
    const float scale = 0.03125f;  // 1024^-0.5

    // x [B,C,L] -> xn [B,L,C], then LN over C
    transpose_k<<<dim3(L_ / 32, C_ / 32, B_), tblk>>>(x, xn, C_, L_);
    ln1024<<<B_ * L_, 256>>>(xn, ln_in_g, ln_in_b, xn);

    // K = xn@Wk, V = xn@Wv   [32768,1024]x[1024,1024]
    sgemm<0, 0, 0, 0, 0><<<dim3(D_ / 128, (B_ * L_) / 128, 1), 256>>>(
        xn, Wk, nullptr, nullptr, kb, B_ * L_, D_, C_, C_, D_, D_, 0, 0, 0, 1.f);
    sgemm<0, 0, 0, 0, 0><<<dim3(D_ / 128, (B_ * L_) / 128, 1), 256>>>(
        xn, Wv, nullptr, nullptr, vb, B_ * L_, D_, C_, C_, D_, D_, 0, 0, 0, 1.f);

    // templates = broadcast(templates_init)
    bcast_tmpl<<<(B_ * N_ * D_) / 256, 256>>>(tinit, tmpl);

    for (int it = 0; it < TIT_; ++it) {
        // t = LN(t_prev); q = (t@Wq)*scale
        ln1024<<<B_ * N_, 256>>>(tmpl, ln_t_g, ln_t_b, tb);
        sgemm<0, 0, 0, 0, 0><<<dim3(D_ / 128, (B_ * N_) / 128, 1), 256>>>(
            tb, Wq, nullptr, nullptr, qb, B_ * N_, D_, D_, D_, D_, D_, 0, 0, 0, scale);

        // logits[b] = K[b] @ q[b]^T : [4096,256], stored in attn buffer
        sgemm<0, 1, 0, 0, 0><<<dim3(N_ / 128, L_ / 128, B_), 256>>>(
            kb, qb, nullptr, nullptr, attn, L_, N_, D_, D_, D_, N_,
            (long long)L_ * D_, (long long)N_ * D_, (long long)L_ * N_, 1.f);

        // softmax over N + 1e-8, then renormalize columns over L
        zero_colsum<<<B_, 256>>>(cs);
        softmax_colsum<<<B_ * L_, 256>>>(attn, cs);
        renorm_div<<<B_ * L_, 256>>>(attn, cs);

        // templates = t_prev + attn^T @ V   (TN GEMM, residual in-place)
        sgemm<1, 0, 0, 0, 1><<<dim3(D_ / 128, N_ / 128, B_), 256>>>(
            attn, vb, nullptr, tmpl, tmpl, N_, D_, L_, N_, D_, D_,
            (long long)L_ * N_, (long long)L_ * D_, (long long)N_ * D_, 1.f);

        // m = LN(templates); templates += relu(m@W1+b1)@W2 + b2
        ln1024<<<B_ * N_, 256>>>(tmpl, ln_m_g, ln_m_b, mb);
        sgemm<0, 0, 1, 1, 0><<<dim3(MLP_ / 128, (B_ * N_) / 128, 1), 256>>>(
            mb, W1, b1, nullptr, hb, B_ * N_, MLP_, D_, D_, MLP_, MLP_, 0, 0, 0, 1.f);
        sgemm<0, 0, 1, 0, 1><<<dim3(D_ / 128, (B_ * N_) / 128, 1), 256>>>(
            hb, W2, b2, tmpl, tmpl, B_ * N_, D_, MLP_, MLP_, D_, D_, 0, 0, 0, 1.f);
    }

    // out_templates [B,D,N]: transpose tmpl [B,N,D]
    transpose_k<<<dim3(D_ / 32, N_ / 32, B_), tblk>>>(tmpl, out, N_, D_);
    // out_attn [B,N,H,W] = attn [B,L,N] transposed
    transpose_k<<<dim3(N_ / 32, L_ / 32, B_), tblk>>>(
        attn, out + (size_t)B_ * D_ * N_, L_, N_);
}

// round 3
// speedup vs baseline: 2.1374x; 2.1374x over previous
#include <cuda_runtime.h>
#include <cstddef>

#define B_    8
#define L_    4096
#define C_    1024
#define D_    1024
#define N_    256
#define MLP_  512
#define TIT_  6

// ---------------- scratch (device globals; no allocation allowed) ----------
__device__ float g_xn  [(size_t)B_ * L_ * C_];
__device__ float g_k   [(size_t)B_ * L_ * D_];
__device__ float g_v   [(size_t)B_ * L_ * D_];
__device__ float g_attn[(size_t)B_ * L_ * N_];
__device__ float g_tmpl[B_ * N_ * D_];
__device__ float g_t   [B_ * N_ * D_];
__device__ float g_q   [B_ * N_ * D_];
__device__ float g_m   [B_ * N_ * D_];
__device__ float g_h   [B_ * N_ * MLP_];
__device__ float g_cs  [B_ * N_];

// ---------------- tf32 helpers ---------------------------------------------
__device__ __forceinline__ float to_tf32(float x) {
    unsigned u;
    asm("cvt.rna.tf32.f32 %0, %1;" : "=r"(u) : "f"(x));
    return __uint_as_float(u);
}
__device__ __forceinline__ float4 cvt4(float4 v) {
    float4 r;
    r.x = to_tf32(v.x); r.y = to_tf32(v.y);
    r.z = to_tf32(v.z); r.w = to_tf32(v.w);
    return r;
}

// ---------------- tf32 tensor-core GEMM -------------------------------------
// C[M,N] = alpha * op(A) op(B) (+bias[n]) (relu) (+resid)
// TA==0: A is [M,K] (lda = row length).  TA==1: A is [K,M].
// TB==0: B is [K,N].                     TB==1: B is [N,K].
// Tile 128x128x32. 8 warps in 2x4; each warp computes 64x32 via m16n8k8 mma.
template<int TA, int TB, int BIAS, int RELU, int RESID>
__global__ void __launch_bounds__(256) tgemm(
    const float* __restrict__ A, const float* __restrict__ Bm,
    const float* __restrict__ bias, const float* __restrict__ Rm,
    float* __restrict__ Cm,
    int M, int N, int K, int lda, int ldb, int ldc,
    long long sA, long long sB, long long sC, float alpha)
{
    // layouts: k-contig rows -> pitch 36 ([row][k]); k-major -> pitch 136 ([k][row])
    __shared__ float As[4608];
    __shared__ float Bs[4608];
    const int bz = blockIdx.z;
    A  += bz * sA;
    Bm += bz * sB;
    Cm += bz * sC;
    const float* Rp = RESID ? (Rm + bz * sC) : nullptr;
    const int m0 = blockIdx.y * 128, n0 = blockIdx.x * 128;
    const int tid = threadIdx.x, lane = tid & 31, wid = tid >> 5;
    const int wm = (wid & 1) * 64, wn = (wid >> 1) * 32;
    const int g = lane >> 2, tig = lane & 3;

    float acc[4][4][4] = {};
    float4 ar[4], br[4];

    auto ldg = [&](int k0) {
#pragma unroll
        for (int i = 0; i < 4; i++) {
            const int li = tid + i * 256;
            if (TA == 0) {
                const int m = li >> 3, kc = (li & 7) * 4;
                ar[i] = *(const float4*)(A + (size_t)(m0 + m) * lda + k0 + kc);
            } else {
                const int kk = li >> 5, mc = (li & 31) * 4;
                ar[i] = *(const float4*)(A + (size_t)(k0 + kk) * lda + m0 + mc);
            }
            if (TB == 0) {
                const int kk = li >> 5, nc = (li & 31) * 4;
                br[i] = *(const float4*)(Bm + (size_t)(k0 + kk) * ldb + n0 + nc);
            } else {
                const int n = li >> 3, kc = (li & 7) * 4;
                br[i] = *(const float4*)(Bm + (size_t)(n0 + n) * ldb + k0 + kc);
            }
        }
    };
    auto sts = [&]() {
#pragma unroll
        for (int i = 0; i < 4; i++) {
            const int li = tid + i * 256;
            const float4 va = cvt4(ar[i]);
            const float4 vb = cvt4(br[i]);
            if (TA == 0) { const int m = li >> 3, kc = (li & 7) * 4;
                           *(float4*)&As[m * 36 + kc] = va; }
            else         { const int kk = li >> 5, mc = (li & 31) * 4;
                           *(float4*)&As[kk * 136 + mc] = va; }
            if (TB == 0) { const int kk = li >> 5, nc = (li & 31) * 4;
                           *(float4*)&Bs[kk * 136 + nc] = vb; }
            else         { const int n = li >> 3, kc = (li & 7) * 4;
                           *(float4*)&Bs[n * 36 + kc] = vb; }
        }
    };
    auto compute = [&]() {
#pragma unroll
        for (int ks = 0; ks < 4; ks++) {
            const int kb = ks * 8;
            unsigned a[4][4], b[4][2];
#pragma unroll
            for (int mt = 0; mt < 4; mt++) {
                const int row = wm + mt * 16 + g;
                if (TA == 0) {
                    a[mt][0] = __float_as_uint(As[row * 36 + kb + tig]);
                    a[mt][1] = __float_as_uint(As[(row + 8) * 36 + kb + tig]);
                    a[mt][2] = __float_as_uint(As[row * 36 + kb + tig + 4]);
                    a[mt][3] = __float_as_uint(As[(row + 8) * 36 + kb + tig + 4]);
                } else {
                    a[mt][0] = __float_as_uint(As[(kb + tig) * 136 + row]);
                    a[mt][1] = __float_as_uint(As[(kb + tig) * 136 + row + 8]);
                    a[mt][2] = __float_as_uint(As[(kb + tig + 4) * 136 + row]);
                    a[mt][3] = __float_as_uint(As[(kb + tig + 4) * 136 + row + 8]);
                }
            }
#pragma unroll
            for (int nt = 0; nt < 4; nt++) {
                const int col = wn + nt * 8 + g;
                if (TB == 0) {
                    b[nt][0] = __float_as_uint(Bs[(kb + tig) * 136 + col]);
                    b[nt][1] = __float_as_uint(Bs[(kb + tig + 4) * 136 + col]);
                } else {
                    b[nt][0] = __float_as_uint(Bs[col * 36 + kb + tig]);
                    b[nt][1] = __float_as_uint(Bs[col * 36 + kb + tig + 4]);
                }
            }
#pragma unroll
            for (int mt = 0; mt < 4; mt++)
#pragma unroll
                for (int nt = 0; nt < 4; nt++)
                    asm volatile(
                        "mma.sync.aligned.m16n8k8.row.col.f32.tf32.tf32.f32 "
                        "{%0,%1,%2,%3}, {%4,%5,%6,%7}, {%8,%9}, {%0,%1,%2,%3};"
                        : "+f"(acc[mt][nt][0]), "+f"(acc[mt][nt][1]),
                          "+f"(acc[mt][nt][2]), "+f"(acc[mt][nt][3])
                        : "r"(a[mt][0]), "r"(a[mt][1]), "r"(a[mt][2]), "r"(a[mt][3]),
                          "r"(b[nt][0]), "r"(b[nt][1]));
        }
    };

    ldg(0);
    sts();
    __syncthreads();
    for (int k0 = 32; k0 < K; k0 += 32) {
        ldg(k0);
        compute();
        __syncthreads();
        sts();
        __syncthreads();
    }
    compute();

#pragma unroll
    for (int mt = 0; mt < 4; mt++) {
        const int r0 = m0 + wm + mt * 16 + g, r1 = r0 + 8;
#pragma unroll
        for (int nt = 0; nt < 4; nt++) {
            const int c = n0 + wn + nt * 8 + tig * 2;
            float v0 = acc[mt][nt][0] * alpha, v1 = acc[mt][nt][1] * alpha;
            float v2 = acc[mt][nt][2] * alpha, v3 = acc[mt][nt][3] * alpha;
            if (BIAS) {
                const float bx = bias[c], by = bias[c + 1];
                v0 += bx; v1 += by; v2 += bx; v3 += by;
            }
            if (RELU) {
                v0 = fmaxf(v0, 0.f); v1 = fmaxf(v1, 0.f);
                v2 = fmaxf(v2, 0.f); v3 = fmaxf(v3, 0.f);
            }
            if (RESID) {
                const float2 p = *(const float2*)(Rp + (size_t)r0 * ldc + c);
                const float2 q = *(const float2*)(Rp + (size_t)r1 * ldc + c);
                v0 += p.x; v1 += p.y; v2 += q.x; v3 += q.y;
            }
            float2 o0; o0.x = v0; o0.y = v1;
            float2 o1; o1.x = v2; o1.y = v3;
            *(float2*)(Cm + (size_t)r0 * ldc + c) = o0;
            *(float2*)(Cm + (size_t)r1 * ldc + c) = o1;
        }
    }
}

// ---------------- LayerNorm over 1024-wide rows ----------------------------
__global__ void __launch_bounds__(256) ln1024(
    const float* __restrict__ in, const float* __restrict__ g,
    const float* __restrict__ b, float* __restrict__ out)
{
    __shared__ float sh[8];
    __shared__ float s_mean, s_rstd;
    const size_t row = blockIdx.x;
    const int t = threadIdx.x;
    const float4 v = ((const float4*)(in + row * 1024))[t];

    float s = v.x + v.y + v.z + v.w;
#pragma unroll
    for (int o = 16; o; o >>= 1) s += __shfl_xor_sync(0xffffffffu, s, o);
    if ((t & 31) == 0) sh[t >> 5] = s;
    __syncthreads();
    if (t == 0) {
        float tt = 0.f;
#pragma unroll
        for (int i = 0; i < 8; i++) tt += sh[i];
        s_mean = tt * (1.f / 1024.f);
    }
    __syncthreads();
    const float mean = s_mean;
    const float dx = v.x - mean, dy = v.y - mean, dz = v.z - mean, dw = v.w - mean;

    float q = dx * dx + dy * dy + dz * dz + dw * dw;
#pragma unroll
    for (int o = 16; o; o >>= 1) q += __shfl_xor_sync(0xffffffffu, q, o);
    __syncthreads();
    if ((t & 31) == 0) sh[t >> 5] = q;
    __syncthreads();
    if (t == 0) {
        float tt = 0.f;
#pragma unroll
        for (int i = 0; i < 8; i++) tt += sh[i];
        s_rstd = rsqrtf(tt * (1.f / 1024.f) + 1e-5f);
    }
    __syncthreads();
    const float rstd = s_rstd;

    const float4 gv = ((const float4*)g)[t];
    const float4 bv = ((const float4*)b)[t];
    float4 o;
    o.x = dx * rstd * gv.x + bv.x;
    o.y = dy * rstd * gv.y + bv.y;
    o.z = dz * rstd * gv.z + bv.z;
    o.w = dw * rstd * gv.w + bv.w;
    ((float4*)(out + row * 1024))[t] = o;
}

// ---------------- softmax over N=256 + column-sum accumulation -------------
__global__ void __launch_bounds__(256) softmax_colsum(
    float* __restrict__ attn, float* __restrict__ colsum)
{
    __shared__ float sh[8];
    __shared__ float s_b;
    const size_t row = blockIdx.x;
    const int n = threadIdx.x;
    const float v = attn[row * 256 + n];

    float m = v;
#pragma unroll
    for (int o = 16; o; o >>= 1) m = fmaxf(m, __shfl_xor_sync(0xffffffffu, m, o));
    if ((n & 31) == 0) sh[n >> 5] = m;
    __syncthreads();
    if (n == 0) {
        float t = sh[0];
#pragma unroll
        for (int i = 1; i < 8; i++) t = fmaxf(t, sh[i]);
        s_b = t;
    }
    __syncthreads();
    const float e = __expf(v - s_b);
    __syncthreads();

    float s = e;
#pragma unroll
    for (int o = 16; o; o >>= 1) s += __shfl_xor_sync(0xffffffffu, s, o);
    if ((n & 31) == 0) sh[n >> 5] = s;
    __syncthreads();
    if (n == 0) {
        float t = 0.f;
#pragma unroll
        for (int i = 0; i < 8; i++) t += sh[i];
        s_b = t;
    }
    __syncthreads();
    const float a = e / s_b + 1e-8f;
    attn[row * 256 + n] = a;
    atomicAdd(&colsum[(row >> 12) * 256 + n], a);
}

__global__ void renorm_div(float* __restrict__ attn, const float* __restrict__ colsum)
{
    const size_t row = blockIdx.x;
    const int n = threadIdx.x;
    attn[row * 256 + n] /= colsum[(row >> 12) * 256 + n];
}

__global__ void zero_colsum(float* __restrict__ p)
{
    p[blockIdx.x * 256 + threadIdx.x] = 0.f;
}

// ---------------- tiled transpose: per batch [R,Cc] -> [Cc,R] --------------
__global__ void transpose_k(const float* __restrict__ in, float* __restrict__ out,
                            int R, int Cc)
{
    __shared__ float tile[32][33];
    const size_t base = (size_t)blockIdx.z * R * Cc;
    const int c0 = blockIdx.x * 32, r0 = blockIdx.y * 32;
#pragma unroll
    for (int i = threadIdx.y; i < 32; i += 8)
        tile[i][threadIdx.x] = in[base + (size_t)(r0 + i) * Cc + c0 + threadIdx.x];
    __syncthreads();
#pragma unroll
    for (int i = threadIdx.y; i < 32; i += 8)
        out[base + (size_t)(c0 + i) * R + r0 + threadIdx.x] = tile[threadIdx.x][i];
}

__global__ void bcast_tmpl(const float* __restrict__ tinit, float* __restrict__ tmpl)
{
    const size_t i = (size_t)blockIdx.x * 256 + threadIdx.x;
    tmpl[i] = tinit[i & ((size_t)N_ * D_ - 1)];
}

// ---------------- host orchestration ---------------------------------------
extern "C" void kernel_launch(void* const* d_in, const int* in_sizes, int n_in,
                              void* d_out, int out_size)
{
    const float* x       = (const float*)d_in[0];
    const float* tinit   = (const float*)d_in[1];
    const float* Wq      = (const float*)d_in[2];
    const float* Wk      = (const float*)d_in[3];
    const float* Wv      = (const float*)d_in[4];
    const float* ln_in_g = (const float*)d_in[5];
    const float* ln_in_b = (const float*)d_in[6];
    const float* ln_t_g  = (const float*)d_in[7];
    const float* ln_t_b  = (const float*)d_in[8];
    const float* ln_m_g  = (const float*)d_in[9];
    const float* ln_m_b  = (const float*)d_in[10];
    const float* W1      = (const float*)d_in[11];
    const float* b1      = (const float*)d_in[12];
    const float* W2      = (const float*)d_in[13];
    const float* b2      = (const float*)d_in[14];
    float* out = (float*)d_out;

    float *xn, *kb, *vb, *attn, *tmpl, *tb, *qb, *mb, *hb, *cs;
    cudaGetSymbolAddress((void**)&xn,   g_xn);
    cudaGetSymbolAddress((void**)&kb,   g_k);
    cudaGetSymbolAddress((void**)&vb,   g_v);
    cudaGetSymbolAddress((void**)&attn, g_attn);
    cudaGetSymbolAddress((void**)&tmpl, g_tmpl);
    cudaGetSymbolAddress((void**)&tb,   g_t);
    cudaGetSymbolAddress((void**)&qb,   g_q);
    cudaGetSymbolAddress((void**)&mb,   g_m);
    cudaGetSymbolAddress((void**)&hb,   g_h);
    cudaGetSymbolAddress((void**)&cs,   g_cs);

    const dim3 tblk(32, 8);
    const float scale = 0.03125f;  // 1024^-0.5

    // x [B,C,L] -> xn [B,L,C], then LN over C
    transpose_k<<<dim3(L_ / 32, C_ / 32, B_), tblk>>>(x, xn, C_, L_);
    ln1024<<<B_ * L_, 256>>>(xn, ln_in_g, ln_in_b, xn);

    // K = xn@Wk, V = xn@Wv   [32768,1024]x[1024,1024]
    tgemm<0, 0, 0, 0, 0><<<dim3(D_ / 128, (B_ * L_) / 128, 1), 256>>>(
        xn, Wk, nullptr, nullptr, kb, B_ * L_, D_, C_, C_, D_, D_, 0, 0, 0, 1.f);
    tgemm<0, 0, 0, 0, 0><<<dim3(D_ / 128, (B_ * L_) / 128, 1), 256>>>(
        xn, Wv, nullptr, nullptr, vb, B_ * L_, D_, C_, C_, D_, D_, 0, 0, 0, 1.f);

    // templates = broadcast(templates_init)
    bcast_tmpl<<<(B_ * N_ * D_) / 256, 256>>>(tinit, tmpl);

    for (int it = 0; it < TIT_; ++it) {
        // t = LN(t_prev); q = (t@Wq)*scale
        ln1024<<<B_ * N_, 256>>>(tmpl, ln_t_g, ln_t_b, tb);
        tgemm<0, 0, 0, 0, 0><<<dim3(D_ / 128, (B_ * N_) / 128, 1), 256>>>(
            tb, Wq, nullptr, nullptr, qb, B_ * N_, D_, D_, D_, D_, D_, 0, 0, 0, scale);

        // logits[b] = K[b] @ q[b]^T : [4096,256]
        tgemm<0, 1, 0, 0, 0><<<dim3(N_ / 128, L_ / 128, B_), 256>>>(
            kb, qb, nullptr, nullptr, attn, L_, N_, D_, D_, D_, N_,
            (long long)L_ * D_, (long long)N_ * D_, (long long)L_ * N_, 1.f);

        // softmax over N + 1e-8, then renormalize columns over L
        zero_colsum<<<B_, 256>>>(cs);
        softmax_colsum<<<B_ * L_, 256>>>(attn, cs);
        renorm_div<<<B_ * L_, 256>>>(attn, cs);

        // templates = t_prev + attn^T @ V   (TN GEMM, residual in-place)
        tgemm<1, 0, 0, 0, 1><<<dim3(D_ / 128, N_ / 128, B_), 256>>>(
            attn, vb, nullptr, tmpl, tmpl, N_, D_, L_, N_, D_, D_,
            (long long)L_ * N_, (long long)L_ * D_, (long long)N_ * D_, 1.f);

        // m = LN(templates); templates += relu(m@W1+b1)@W2 + b2
        ln1024<<<B_ * N_, 256>>>(tmpl, ln_m_g, ln_m_b, mb);
        tgemm<0, 0, 1, 1, 0><<<dim3(MLP_ / 128, (B_ * N_) / 128, 1), 256>>>(
            mb, W1, b1, nullptr, hb, B_ * N_, MLP_, D_, D_, MLP_, MLP_, 0, 0, 0, 1.f);
        tgemm<0, 0, 1, 0, 1><<<dim3(D_ / 128, (B_ * N_) / 128, 1), 256>>>(
            hb, W2, b2, tmpl, tmpl, B_ * N_, D_, MLP_, MLP_, D_, D_, 0, 0, 0, 1.f);
    }

    // out_templates [B,D,N]: transpose tmpl [B,N,D]
    transpose_k<<<dim3(D_ / 32, N_ / 32, B_), tblk>>>(tmpl, out, N_, D_);
    // out_attn [B,N,H,W] = attn [B,L,N] transposed
    transpose_k<<<dim3(N_ / 32, L_ / 32, B_), tblk>>>(
        attn, out + (size_t)B_ * D_ * N_, L_, N_);
}

// round 4
// speedup vs baseline: 2.8115x; 1.3154x over previous
#include <cuda_runtime.h>
#include <cstddef>

#define B_    8
#define L_    4096
#define C_    1024
#define D_    1024
#define N_    256
#define MLP_  512
#define TIT_  6

// ---------------- scratch (device globals; no allocation allowed) ----------
__device__ float g_xn  [(size_t)B_ * L_ * C_];
__device__ float g_k   [(size_t)B_ * L_ * D_];
__device__ float g_v   [(size_t)B_ * L_ * D_];
__device__ float g_attn[(size_t)B_ * L_ * N_];
__device__ float g_tmpl[B_ * N_ * D_];
__device__ float g_t   [B_ * N_ * D_];
__device__ float g_q   [B_ * N_ * D_];
__device__ float g_m   [B_ * N_ * D_];
__device__ float g_h   [B_ * N_ * MLP_];
__device__ float g_cs  [B_ * N_];
__device__ float g_wq  [D_ * D_];
__device__ float g_wk  [C_ * D_];
__device__ float g_wv  [C_ * D_];
__device__ float g_w1  [D_ * MLP_];
__device__ float g_w2  [MLP_ * D_];

// ---------------- tf32 helpers ---------------------------------------------
__device__ __forceinline__ float to_tf32(float x) {
    unsigned u;
    asm("cvt.rna.tf32.f32 %0, %1;" : "=r"(u) : "f"(x));
    return __uint_as_float(u);
}

__device__ __forceinline__ void cp16(void* smem_dst, const void* gmem_src) {
    unsigned s = (unsigned)__cvta_generic_to_shared(smem_dst);
    asm volatile("cp.async.cg.shared.global [%0], [%1], 16;\n"
                 :: "r"(s), "l"(gmem_src));
}

// ---------------- tf32 tensor-core GEMM, cp.async double-buffered -----------
// C[M,N] = alpha * op(A) op(B) (+bias[n]) (relu) (+resid), optional tf32-round
// TA==0: A is [M,K].  TA==1: A is [K,M].
// TB==0: B is [K,N].  TB==1: B is [N,K].
// CTA tile 128x128x32, 4 warps (2x2), each warp 64x64 via m16n8k8 tf32 mma.
// Inputs assumed already tf32-rounded (or rely on HW truncation).
#define ASTRIDE 4608
template<int TA, int TB, int BIAS, int RELU, int RESID, int CVT>
__global__ void __launch_bounds__(128, 2) tgemm(
    const float* __restrict__ A, const float* __restrict__ Bm,
    const float* __restrict__ bias, const float* __restrict__ Rm,
    float* __restrict__ Cm,
    int M, int N, int K, int lda, int ldb, int ldc,
    long long sA, long long sB, long long sC, float alpha)
{
    extern __shared__ float sm[];
    float* As = sm;                 // 2 stages x 4608
    float* Bs = sm + 2 * ASTRIDE;   // 2 stages x 4608
    const int bz = blockIdx.z;
    A  += bz * sA;
    Bm += bz * sB;
    Cm += bz * sC;
    const float* Rp = RESID ? (Rm + bz * sC) : nullptr;
    const int m0 = blockIdx.y * 128, n0 = blockIdx.x * 128;
    const int tid = threadIdx.x, lane = tid & 31, wid = tid >> 5;
    const int wm = (wid & 1) * 64, wn = (wid >> 1) * 64;
    const int g = lane >> 2, tig = lane & 3;

    float acc[4][8][4] = {};

    auto load_stage = [&](int k0, int s) {
        float* Ad = As + s * ASTRIDE;
        float* Bd = Bs + s * ASTRIDE;
#pragma unroll
        for (int i = 0; i < 8; i++) {
            const int c = tid + i * 128;
            if (TA == 0) {
                const int row = c >> 3, kc = (c & 7) * 4;
                cp16(Ad + row * 36 + kc, A + (size_t)(m0 + row) * lda + k0 + kc);
            } else {
                const int kk = c >> 5, mc = (c & 31) * 4;
                cp16(Ad + kk * 136 + mc, A + (size_t)(k0 + kk) * lda + m0 + mc);
            }
            if (TB == 0) {
                const int kk = c >> 5, nc = (c & 31) * 4;
                cp16(Bd + kk * 136 + nc, Bm + (size_t)(k0 + kk) * ldb + n0 + nc);
            } else {
                const int row = c >> 3, kc = (c & 7) * 4;
                cp16(Bd + row * 36 + kc, Bm + (size_t)(n0 + row) * ldb + k0 + kc);
            }
        }
        asm volatile("cp.async.commit_group;\n");
    };

    auto compute = [&](int s) {
        const float* Ab = As + s * ASTRIDE;
        const float* Bb = Bs + s * ASTRIDE;
#pragma unroll
        for (int ks = 0; ks < 4; ks++) {
            const int kb = ks * 8;
            unsigned a[4][4], b[8][2];
#pragma unroll
            for (int mt = 0; mt < 4; mt++) {
                const int row = wm + mt * 16 + g;
                if (TA == 0) {
                    const int base = row * 36 + kb + tig;
                    a[mt][0] = __float_as_uint(Ab[base]);
                    a[mt][1] = __float_as_uint(Ab[base + 8 * 36]);
                    a[mt][2] = __float_as_uint(Ab[base + 4]);
                    a[mt][3] = __float_as_uint(Ab[base + 8 * 36 + 4]);
                } else {
                    const int base = (kb + tig) * 136 + row;
                    a[mt][0] = __float_as_uint(Ab[base]);
                    a[mt][1] = __float_as_uint(Ab[base + 8]);
                    a[mt][2] = __float_as_uint(Ab[base + 4 * 136]);
                    a[mt][3] = __float_as_uint(Ab[base + 4 * 136 + 8]);
                }
            }
#pragma unroll
            for (int nt = 0; nt < 8; nt++) {
                const int col = wn + nt * 8 + g;
                if (TB == 0) {
                    b[nt][0] = __float_as_uint(Bb[(kb + tig) * 136 + col]);
                    b[nt][1] = __float_as_uint(Bb[(kb + tig + 4) * 136 + col]);
                } else {
                    b[nt][0] = __float_as_uint(Bb[col * 36 + kb + tig]);
                    b[nt][1] = __float_as_uint(Bb[col * 36 + kb + tig + 4]);
                }
            }
#pragma unroll
            for (int mt = 0; mt < 4; mt++)
#pragma unroll
                for (int nt = 0; nt < 8; nt++)
                    asm volatile(
                        "mma.sync.aligned.m16n8k8.row.col.f32.tf32.tf32.f32 "
                        "{%0,%1,%2,%3}, {%4,%5,%6,%7}, {%8,%9}, {%0,%1,%2,%3};"
                        : "+f"(acc[mt][nt][0]), "+f"(acc[mt][nt][1]),
                          "+f"(acc[mt][nt][2]), "+f"(acc[mt][nt][3])
                        : "r"(a[mt][0]), "r"(a[mt][1]), "r"(a[mt][2]), "r"(a[mt][3]),
                          "r"(b[nt][0]), "r"(b[nt][1]));
        }
    };

    load_stage(0, 0);
    const int T = K >> 5;
    for (int t = 0; t < T; t++) {
        asm volatile("cp.async.wait_group 0;\n");
        __syncthreads();
        if (t + 1 < T) load_stage((t + 1) << 5, (t + 1) & 1);
        compute(t & 1);
    }

#pragma unroll
    for (int mt = 0; mt < 4; mt++) {
        const int r0 = m0 + wm + mt * 16 + g, r1 = r0 + 8;
#pragma unroll
        for (int nt = 0; nt < 8; nt++) {
            const int c = n0 + wn + nt * 8 + tig * 2;
            float v0 = acc[mt][nt][0] * alpha, v1 = acc[mt][nt][1] * alpha;
            float v2 = acc[mt][nt][2] * alpha, v3 = acc[mt][nt][3] * alpha;
            if (BIAS) {
                const float bx = bias[c], by = bias[c + 1];
                v0 += bx; v1 += by; v2 += bx; v3 += by;
            }
            if (RELU) {
                v0 = fmaxf(v0, 0.f); v1 = fmaxf(v1, 0.f);
                v2 = fmaxf(v2, 0.f); v3 = fmaxf(v3, 0.f);
            }
            if (RESID) {
                const float2 p = *(const float2*)(Rp + (size_t)r0 * ldc + c);
                const float2 q = *(const float2*)(Rp + (size_t)r1 * ldc + c);
                v0 += p.x; v1 += p.y; v2 += q.x; v3 += q.y;
            }
            if (CVT) {
                v0 = to_tf32(v0); v1 = to_tf32(v1);
                v2 = to_tf32(v2); v3 = to_tf32(v3);
            }
            float2 o0; o0.x = v0; o0.y = v1;
            float2 o1; o1.x = v2; o1.y = v3;
            *(float2*)(Cm + (size_t)r0 * ldc + c) = o0;
            *(float2*)(Cm + (size_t)r1 * ldc + c) = o1;
        }
    }
}

// ---------------- LayerNorm over 1024-wide rows (tf32-rounded output) -------
__global__ void __launch_bounds__(256) ln1024(
    const float* __restrict__ in, const float* __restrict__ g,
    const float* __restrict__ b, float* __restrict__ out)
{
    __shared__ float sh[8];
    __shared__ float s_mean, s_rstd;
    const size_t row = blockIdx.x;
    const int t = threadIdx.x;
    const float4 v = ((const float4*)(in + row * 1024))[t];

    float s = v.x + v.y + v.z + v.w;
#pragma unroll
    for (int o = 16; o; o >>= 1) s += __shfl_xor_sync(0xffffffffu, s, o);
    if ((t & 31) == 0) sh[t >> 5] = s;
    __syncthreads();
    if (t == 0) {
        float tt = 0.f;
#pragma unroll
        for (int i = 0; i < 8; i++) tt += sh[i];
        s_mean = tt * (1.f / 1024.f);
    }
    __syncthreads();
    const float mean = s_mean;
    const float dx = v.x - mean, dy = v.y - mean, dz = v.z - mean, dw = v.w - mean;

    float q = dx * dx + dy * dy + dz * dz + dw * dw;
#pragma unroll
    for (int o = 16; o; o >>= 1) q += __shfl_xor_sync(0xffffffffu, q, o);
    __syncthreads();
    if ((t & 31) == 0) sh[t >> 5] = q;
    __syncthreads();
    if (t == 0) {
        float tt = 0.f;
#pragma unroll
        for (int i = 0; i < 8; i++) tt += sh[i];
        s_rstd = rsqrtf(tt * (1.f / 1024.f) + 1e-5f);
    }
    __syncthreads();
    const float rstd = s_rstd;

    const float4 gv = ((const float4*)g)[t];
    const float4 bv = ((const float4*)b)[t];
    float4 o;
    o.x = to_tf32(dx * rstd * gv.x + bv.x);
    o.y = to_tf32(dy * rstd * gv.y + bv.y);
    o.z = to_tf32(dz * rstd * gv.z + bv.z);
    o.w = to_tf32(dw * rstd * gv.w + bv.w);
    ((float4*)(out + row * 1024))[t] = o;
}

// ---------------- softmax over N=256 + column-sum accumulation -------------
__global__ void __launch_bounds__(256) softmax_colsum(
    float* __restrict__ attn, float* __restrict__ colsum)
{
    __shared__ float sh[8];
    __shared__ float s_b;
    const size_t row = blockIdx.x;
    const int n = threadIdx.x;
    const float v = attn[row * 256 + n];

    float m = v;
#pragma unroll
    for (int o = 16; o; o >>= 1) m = fmaxf(m, __shfl_xor_sync(0xffffffffu, m, o));
    if ((n & 31) == 0) sh[n >> 5] = m;
    __syncthreads();
    if (n == 0) {
        float t = sh[0];
#pragma unroll
        for (int i = 1; i < 8; i++) t = fmaxf(t, sh[i]);
        s_b = t;
    }
    __syncthreads();
    const float e = __expf(v - s_b);
    __syncthreads();

    float s = e;
#pragma unroll
    for (int o = 16; o; o >>= 1) s += __shfl_xor_sync(0xffffffffu, s, o);
    if ((n & 31) == 0) sh[n >> 5] = s;
    __syncthreads();
    if (n == 0) {
        float t = 0.f;
#pragma unroll
        for (int i = 0; i < 8; i++) t += sh[i];
        s_b = t;
    }
    __syncthreads();
    const float a = e / s_b + 1e-8f;
    attn[row * 256 + n] = a;
    atomicAdd(&colsum[(row >> 12) * 256 + n], a);
}

__global__ void renorm_div(float* __restrict__ attn, const float* __restrict__ colsum)
{
    const size_t row = blockIdx.x;
    const int n = threadIdx.x;
    attn[row * 256 + n] /= colsum[(row >> 12) * 256 + n];
}

__global__ void zero_colsum(float* __restrict__ p)
{
    p[blockIdx.x * 256 + threadIdx.x] = 0.f;
}

// ---------------- tiled transpose: per batch [R,Cc] -> [Cc,R] --------------
__global__ void transpose_k(const float* __restrict__ in, float* __restrict__ out,
                            int R, int Cc)
{
    __shared__ float tile[32][33];
    const size_t base = (size_t)blockIdx.z * R * Cc;
    const int c0 = blockIdx.x * 32, r0 = blockIdx.y * 32;
#pragma unroll
    for (int i = threadIdx.y; i < 32; i += 8)
        tile[i][threadIdx.x] = in[base + (size_t)(r0 + i) * Cc + c0 + threadIdx.x];
    __syncthreads();
#pragma unroll
    for (int i = threadIdx.y; i < 32; i += 8)
        out[base + (size_t)(c0 + i) * R + r0 + threadIdx.x] = tile[threadIdx.x][i];
}

__global__ void bcast_tmpl(const float* __restrict__ tinit, float* __restrict__ tmpl)
{
    const size_t i = (size_t)blockIdx.x * 256 + threadIdx.x;
    tmpl[i] = tinit[i & ((size_t)N_ * D_ - 1)];
}

__global__ void round_copy(const float* __restrict__ in, float* __restrict__ out)
{
    const size_t i = (size_t)blockIdx.x * 256 + threadIdx.x;
    out[i] = to_tf32(in[i]);
}

// ---------------- host orchestration ---------------------------------------
extern "C" void kernel_launch(void* const* d_in, const int* in_sizes, int n_in,
                              void* d_out, int out_size)
{
    const float* x       = (const float*)d_in[0];
    const float* tinit   = (const float*)d_in[1];
    const float* Wq      = (const float*)d_in[2];
    const float* Wk      = (const float*)d_in[3];
    const float* Wv      = (const float*)d_in[4];
    const float* ln_in_g = (const float*)d_in[5];
    const float* ln_in_b = (const float*)d_in[6];
    const float* ln_t_g  = (const float*)d_in[7];
    const float* ln_t_b  = (const float*)d_in[8];
    const float* ln_m_g  = (const float*)d_in[9];
    const float* ln_m_b  = (const float*)d_in[10];
    const float* W1      = (const float*)d_in[11];
    const float* b1      = (const float*)d_in[12];
    const float* W2      = (const float*)d_in[13];
    const float* b2      = (const float*)d_in[14];
    float* out = (float*)d_out;

    float *xn, *kb, *vb, *attn, *tmpl, *tb, *qb, *mb, *hb, *cs;
    float *wq, *wk, *wv, *w1, *w2;
    cudaGetSymbolAddress((void**)&xn,   g_xn);
    cudaGetSymbolAddress((void**)&kb,   g_k);
    cudaGetSymbolAddress((void**)&vb,   g_v);
    cudaGetSymbolAddress((void**)&attn, g_attn);
    cudaGetSymbolAddress((void**)&tmpl, g_tmpl);
    cudaGetSymbolAddress((void**)&tb,   g_t);
    cudaGetSymbolAddress((void**)&qb,   g_q);
    cudaGetSymbolAddress((void**)&mb,   g_m);
    cudaGetSymbolAddress((void**)&hb,   g_h);
    cudaGetSymbolAddress((void**)&cs,   g_cs);
    cudaGetSymbolAddress((void**)&wq,   g_wq);
    cudaGetSymbolAddress((void**)&wk,   g_wk);
    cudaGetSymbolAddress((void**)&wv,   g_wv);
    cudaGetSymbolAddress((void**)&w1,   g_w1);
    cudaGetSymbolAddress((void**)&w2,   g_w2);

    const int SMEM = 4 * ASTRIDE * (int)sizeof(float);  // 73728
    cudaFuncSetAttribute(tgemm<0,0,0,0,0,1>, cudaFuncAttributeMaxDynamicSharedMemorySize, SMEM);
    cudaFuncSetAttribute(tgemm<0,1,0,0,0,0>, cudaFuncAttributeMaxDynamicSharedMemorySize, SMEM);
    cudaFuncSetAttribute(tgemm<1,0,0,0,1,0>, cudaFuncAttributeMaxDynamicSharedMemorySize, SMEM);
    cudaFuncSetAttribute(tgemm<0,0,1,1,0,1>, cudaFuncAttributeMaxDynamicSharedMemorySize, SMEM);
    cudaFuncSetAttribute(tgemm<0,0,1,0,1,0>, cudaFuncAttributeMaxDynamicSharedMemorySize, SMEM);

    const dim3 tblk(32, 8);
    const float scale = 0.03125f;  // 1024^-0.5

    // pre-round weights to tf32 (one pass; consumed by all GEMMs)
    round_copy<<<(D_ * D_)   / 256, 256>>>(Wq, wq);
    round_copy<<<(C_ * D_)   / 256, 256>>>(Wk, wk);
    round_copy<<<(C_ * D_)   / 256, 256>>>(Wv, wv);
    round_copy<<<(D_ * MLP_) / 256, 256>>>(W1, w1);
    round_copy<<<(MLP_ * D_) / 256, 256>>>(W2, w2);

    // x [B,C,L] -> xn [B,L,C], then LN over C (rounded output)
    transpose_k<<<dim3(L_ / 32, C_ / 32, B_), tblk>>>(x, xn, C_, L_);
    ln1024<<<B_ * L_, 256>>>(xn, ln_in_g, ln_in_b, xn);

    // K = xn@Wk, V = xn@Wv   [32768,1024]x[1024,1024], tf32-rounded outputs
    tgemm<0,0,0,0,0,1><<<dim3(D_ / 128, (B_ * L_) / 128, 1), 128, SMEM>>>(
        xn, wk, nullptr, nullptr, kb, B_ * L_, D_, C_, C_, D_, D_, 0, 0, 0, 1.f);
    tgemm<0,0,0,0,0,1><<<dim3(D_ / 128, (B_ * L_) / 128, 1), 128, SMEM>>>(
        xn, wv, nullptr, nullptr, vb, B_ * L_, D_, C_, C_, D_, D_, 0, 0, 0, 1.f);

    // templates = broadcast(templates_init)
    bcast_tmpl<<<(B_ * N_ * D_) / 256, 256>>>(tinit, tmpl);

    for (int it = 0; it < TIT_; ++it) {
        // t = LN(t_prev); q = (t@Wq)*scale  (rounded)
        ln1024<<<B_ * N_, 256>>>(tmpl, ln_t_g, ln_t_b, tb);
        tgemm<0,0,0,0,0,1><<<dim3(D_ / 128, (B_ * N_) / 128, 1), 128, SMEM>>>(
            tb, wq, nullptr, nullptr, qb, B_ * N_, D_, D_, D_, D_, D_, 0, 0, 0, scale);

        // logits[b] = K[b] @ q[b]^T : [4096,256]  (full fp32 out)
        tgemm<0,1,0,0,0,0><<<dim3(N_ / 128, L_ / 128, B_), 128, SMEM>>>(
            kb, qb, nullptr, nullptr, attn, L_, N_, D_, D_, D_, N_,
            (long long)L_ * D_, (long long)N_ * D_, (long long)L_ * N_, 1.f);

        // softmax over N + 1e-8, then renormalize columns over L
        zero_colsum<<<B_, 256>>>(cs);
        softmax_colsum<<<B_ * L_, 256>>>(attn, cs);
        renorm_div<<<B_ * L_, 256>>>(attn, cs);

        // templates = t_prev + attn^T @ V (attn operand HW-truncated to tf32)
        tgemm<1,0,0,0,1,0><<<dim3(D_ / 128, N_ / 128, B_), 128, SMEM>>>(
            attn, vb, nullptr, tmpl, tmpl, N_, D_, L_, N_, D_, D_,
            (long long)L_ * N_, (long long)L_ * D_, (long long)N_ * D_, 1.f);

        // m = LN(templates); templates += relu(m@W1+b1)@W2 + b2
        ln1024<<<B_ * N_, 256>>>(tmpl, ln_m_g, ln_m_b, mb);
        tgemm<0,0,1,1,0,1><<<dim3(MLP_ / 128, (B_ * N_) / 128, 1), 128, SMEM>>>(
            mb, w1, b1, nullptr, hb, B_ * N_, MLP_, D_, D_, MLP_, MLP_, 0, 0, 0, 1.f);
        tgemm<0,0,1,0,1,0><<<dim3(D_ / 128, (B_ * N_) / 128, 1), 128, SMEM>>>(
            hb, w2, b2, tmpl, tmpl, B_ * N_, D_, MLP_, MLP_, D_, D_, 0, 0, 0, 1.f);
    }

    // out_templates [B,D,N]: transpose tmpl [B,N,D]
    transpose_k<<<dim3(D_ / 32, N_ / 32, B_), tblk>>>(tmpl, out, N_, D_);
    // out_attn [B,N,H,W] = attn [B,L,N] transposed
    transpose_k<<<dim3(N_ / 32, L_ / 32, B_), tblk>>>(
        attn, out + (size_t)B_ * D_ * N_, L_, N_);
}

// round 5
// speedup vs baseline: 2.9419x; 1.0464x over previous
#include <cuda_runtime.h>
#include <cstddef>

#define B_    8
#define L_    4096
#define C_    1024
#define D_    1024
#define N_    256
#define MLP_  512
#define TIT_  6

// ---------------- scratch (device globals; no allocation allowed) ----------
__device__ float g_xn  [(size_t)B_ * L_ * C_];
__device__ float g_k   [(size_t)B_ * L_ * D_];
__device__ float g_v   [(size_t)B_ * L_ * D_];
__device__ float g_attn[(size_t)B_ * L_ * N_];
__device__ float g_tmpl[B_ * N_ * D_];
__device__ float g_t   [B_ * N_ * D_];
__device__ float g_q   [B_ * N_ * D_];
__device__ float g_m   [B_ * N_ * D_];
__device__ float g_h   [B_ * N_ * MLP_];
__device__ float g_upd [B_ * N_ * D_];
__device__ float g_cs  [B_ * N_];
__device__ float g_wq  [D_ * D_];
__device__ float g_wk  [C_ * D_];
__device__ float g_wv  [C_ * D_];
__device__ float g_w1  [D_ * MLP_];
__device__ float g_w2  [MLP_ * D_];

// ---------------- tf32 helpers ---------------------------------------------
__device__ __forceinline__ float to_tf32(float x) {
    unsigned u;
    asm("cvt.rna.tf32.f32 %0, %1;" : "=r"(u) : "f"(x));
    return __uint_as_float(u);
}

__device__ __forceinline__ void cp16(void* smem_dst, const void* gmem_src) {
    unsigned s = (unsigned)__cvta_generic_to_shared(smem_dst);
    asm volatile("cp.async.cg.shared.global [%0], [%1], 16;\n"
                 :: "r"(s), "l"(gmem_src));
}

// ---------------- tf32 tensor-core GEMM, cp.async double-buffered -----------
// C[M,N] = alpha * op(A) op(B) (+bias) (relu) (+resid) | atomicAdd partials
// TA==0: A is [M,K].  TA==1: A is [K,M].
// TB==0: B is [K,N].  TB==1: B is [N,K].
// CTA tile BM x 128 x 32, 4 warps, warp tile (BM/2) x 64 via m16n8k8 tf32 mma.
// SPLITK>1: blockIdx.z = batch*SPLITK + split; partials atomicAdd'ed (ATOMIC=1).
template<int BM, int TA, int TB, int BIAS, int RELU, int RESID, int CVT,
         int SPLITK, int ATOMIC>
__global__ void __launch_bounds__(128, 2) tgemm(
    const float* __restrict__ A, const float* __restrict__ Bm,
    const float* __restrict__ bias, const float* __restrict__ Rm,
    float* __restrict__ Cm,
    int M, int N, int K, int lda, int ldb, int ldc,
    long long sA, long long sB, long long sC, float alpha)
{
    constexpr int AST = (TA == 0) ? BM * 36 : 32 * (BM + 8);
    constexpr int BST = (TB == 0) ? 32 * 136 : 128 * 36;
    constexpr int MT  = BM / 32;          // m-frag count per warp
    constexpr int NA4 = BM / 16;          // A float4 loads per thread
    extern __shared__ float sm[];
    float* As = sm;
    float* Bs = sm + 2 * AST;

    int bz = blockIdx.z, batch = bz, koff = 0;
    if (SPLITK > 1) { batch = bz / SPLITK; koff = (bz % SPLITK) * (K / SPLITK); }
    A  += (size_t)batch * sA + (TA ? (size_t)koff * lda : (size_t)koff);
    Bm += (size_t)batch * sB + (TB ? (size_t)koff : (size_t)koff * ldb);
    Cm += (size_t)batch * sC;
    const float* Rp = RESID ? (Rm + (size_t)batch * sC) : nullptr;

    const int m0 = blockIdx.y * BM, n0 = blockIdx.x * 128;
    const int tid = threadIdx.x, lane = tid & 31, wid = tid >> 5;
    const int wm = (wid & 1) * (BM / 2), wn = (wid >> 1) * 64;
    const int g = lane >> 2, tig = lane & 3;

    float acc[MT][8][4] = {};

    auto load_stage = [&](int k0, int s) {
        float* Ad = As + s * AST;
        float* Bd = Bs + s * BST;
#pragma unroll
        for (int i = 0; i < 8; i++) {
            const int c = tid + i * 128;
            if (i < NA4) {
                if (TA == 0) {
                    const int row = c >> 3, kc = (c & 7) * 4;
                    cp16(Ad + row * 36 + kc, A + (size_t)(m0 + row) * lda + k0 + kc);
                } else {
                    const int kk = c / (BM / 4), mc = (c % (BM / 4)) * 4;
                    cp16(Ad + kk * (BM + 8) + mc, A + (size_t)(k0 + kk) * lda + m0 + mc);
                }
            }
            if (TB == 0) {
                const int kk = c >> 5, nc = (c & 31) * 4;
                cp16(Bd + kk * 136 + nc, Bm + (size_t)(k0 + kk) * ldb + n0 + nc);
            } else {
                const int row = c >> 3, kc = (c & 7) * 4;
                cp16(Bd + row * 36 + kc, Bm + (size_t)(n0 + row) * ldb + k0 + kc);
            }
        }
        asm volatile("cp.async.commit_group;\n");
    };

    auto compute = [&](int s) {
        const float* Ab = As + s * AST;
        const float* Bb = Bs + s * BST;
#pragma unroll
        for (int ks = 0; ks < 4; ks++) {
            const int kb = ks * 8;
            unsigned a[MT][4], b[8][2];
#pragma unroll
            for (int mt = 0; mt < MT; mt++) {
                const int row = wm + mt * 16 + g;
                if (TA == 0) {
                    const int base = row * 36 + kb + tig;
                    a[mt][0] = __float_as_uint(Ab[base]);
                    a[mt][1] = __float_as_uint(Ab[base + 8 * 36]);
                    a[mt][2] = __float_as_uint(Ab[base + 4]);
                    a[mt][3] = __float_as_uint(Ab[base + 8 * 36 + 4]);
                } else {
                    const int base = (kb + tig) * (BM + 8) + row;
                    a[mt][0] = __float_as_uint(Ab[base]);
                    a[mt][1] = __float_as_uint(Ab[base + 8]);
                    a[mt][2] = __float_as_uint(Ab[base + 4 * (BM + 8)]);
                    a[mt][3] = __float_as_uint(Ab[base + 4 * (BM + 8) + 8]);
                }
            }
#pragma unroll
            for (int nt = 0; nt < 8; nt++) {
                const int col = wn + nt * 8 + g;
                if (TB == 0) {
                    b[nt][0] = __float_as_uint(Bb[(kb + tig) * 136 + col]);
                    b[nt][1] = __float_as_uint(Bb[(kb + tig + 4) * 136 + col]);
                } else {
                    b[nt][0] = __float_as_uint(Bb[col * 36 + kb + tig]);
                    b[nt][1] = __float_as_uint(Bb[col * 36 + kb + tig + 4]);
                }
            }
#pragma unroll
            for (int mt = 0; mt < MT; mt++)
#pragma unroll
                for (int nt = 0; nt < 8; nt++)
                    asm volatile(
                        "mma.sync.aligned.m16n8k8.row.col.f32.tf32.tf32.f32 "
                        "{%0,%1,%2,%3}, {%4,%5,%6,%7}, {%8,%9}, {%0,%1,%2,%3};"
                        : "+f"(acc[mt][nt][0]), "+f"(acc[mt][nt][1]),
                          "+f"(acc[mt][nt][2]), "+f"(acc[mt][nt][3])
                        : "r"(a[mt][0]), "r"(a[mt][1]), "r"(a[mt][2]), "r"(a[mt][3]),
                          "r"(b[nt][0]), "r"(b[nt][1]));
        }
    };

    load_stage(0, 0);
    const int T = ((SPLITK > 1) ? K / SPLITK : K) >> 5;
    for (int t = 0; t < T; t++) {
        asm volatile("cp.async.wait_group 0;\n");
        __syncthreads();
        if (t + 1 < T) load_stage((t + 1) << 5, (t + 1) & 1);
        compute(t & 1);
    }

#pragma unroll
    for (int mt = 0; mt < MT; mt++) {
        const int r0 = m0 + wm + mt * 16 + g, r1 = r0 + 8;
#pragma unroll
        for (int nt = 0; nt < 8; nt++) {
            const int c = n0 + wn + nt * 8 + tig * 2;
            float v0 = acc[mt][nt][0] * alpha, v1 = acc[mt][nt][1] * alpha;
            float v2 = acc[mt][nt][2] * alpha, v3 = acc[mt][nt][3] * alpha;
            if (ATOMIC) {
                atomicAdd(Cm + (size_t)r0 * ldc + c,     v0);
                atomicAdd(Cm + (size_t)r0 * ldc + c + 1, v1);
                atomicAdd(Cm + (size_t)r1 * ldc + c,     v2);
                atomicAdd(Cm + (size_t)r1 * ldc + c + 1, v3);
                continue;
            }
            if (BIAS) {
                const float bx = bias[c], by = bias[c + 1];
                v0 += bx; v1 += by; v2 += bx; v3 += by;
            }
            if (RELU) {
                v0 = fmaxf(v0, 0.f); v1 = fmaxf(v1, 0.f);
                v2 = fmaxf(v2, 0.f); v3 = fmaxf(v3, 0.f);
            }
            if (RESID) {
                const float2 p = *(const float2*)(Rp + (size_t)r0 * ldc + c);
                const float2 q = *(const float2*)(Rp + (size_t)r1 * ldc + c);
                v0 += p.x; v1 += p.y; v2 += q.x; v3 += q.y;
            }
            if (CVT) {
                v0 = to_tf32(v0); v1 = to_tf32(v1);
                v2 = to_tf32(v2); v3 = to_tf32(v3);
            }
            float2 o0; o0.x = v0; o0.y = v1;
            float2 o1; o1.x = v2; o1.y = v3;
            *(float2*)(Cm + (size_t)r0 * ldc + c) = o0;
            *(float2*)(Cm + (size_t)r1 * ldc + c) = o1;
        }
    }
}

// ---------------- LayerNorm over 1024-wide rows (tf32-rounded output) -------
__global__ void __launch_bounds__(256) ln1024(
    const float* __restrict__ in, const float* __restrict__ g,
    const float* __restrict__ b, float* __restrict__ out)
{
    __shared__ float sh[8];
    __shared__ float s_mean, s_rstd;
    const size_t row = blockIdx.x;
    const int t = threadIdx.x;
    const float4 v = ((const float4*)(in + row * 1024))[t];

    float s = v.x + v.y + v.z + v.w;
#pragma unroll
    for (int o = 16; o; o >>= 1) s += __shfl_xor_sync(0xffffffffu, s, o);
    if ((t & 31) == 0) sh[t >> 5] = s;
    __syncthreads();
    if (t == 0) {
        float tt = 0.f;
#pragma unroll
        for (int i = 0; i < 8; i++) tt += sh[i];
        s_mean = tt * (1.f / 1024.f);
    }
    __syncthreads();
    const float mean = s_mean;
    const float dx = v.x - mean, dy = v.y - mean, dz = v.z - mean, dw = v.w - mean;

    float q = dx * dx + dy * dy + dz * dz + dw * dw;
#pragma unroll
    for (int o = 16; o; o >>= 1) q += __shfl_xor_sync(0xffffffffu, q, o);
    __syncthreads();
    if ((t & 31) == 0) sh[t >> 5] = q;
    __syncthreads();
    if (t == 0) {
        float tt = 0.f;
#pragma unroll
        for (int i = 0; i < 8; i++) tt += sh[i];
        s_rstd = rsqrtf(tt * (1.f / 1024.f) + 1e-5f);
    }
    __syncthreads();
    const float rstd = s_rstd;

    const float4 gv = ((const float4*)g)[t];
    const float4 bv = ((const float4*)b)[t];
    float4 o;
    o.x = to_tf32(dx * rstd * gv.x + bv.x);
    o.y = to_tf32(dy * rstd * gv.y + bv.y);
    o.z = to_tf32(dz * rstd * gv.z + bv.z);
    o.w = to_tf32(dw * rstd * gv.w + bv.w);
    ((float4*)(out + row * 1024))[t] = o;
}

// ---------------- softmax over N=256 + column-sum accumulation -------------
__global__ void __launch_bounds__(256) softmax_colsum(
    float* __restrict__ attn, float* __restrict__ colsum)
{
    __shared__ float sh[8];
    __shared__ float s_b;
    const size_t row = blockIdx.x;
    const int n = threadIdx.x;
    const float v = attn[row * 256 + n];

    float m = v;
#pragma unroll
    for (int o = 16; o; o >>= 1) m = fmaxf(m, __shfl_xor_sync(0xffffffffu, m, o));
    if ((n & 31) == 0) sh[n >> 5] = m;
    __syncthreads();
    if (n == 0) {
        float t = sh[0];
#pragma unroll
        for (int i = 1; i < 8; i++) t = fmaxf(t, sh[i]);
        s_b = t;
    }
    __syncthreads();
    const float e = __expf(v - s_b);
    __syncthreads();

    float s = e;
#pragma unroll
    for (int o = 16; o; o >>= 1) s += __shfl_xor_sync(0xffffffffu, s, o);
    if ((n & 31) == 0) sh[n >> 5] = s;
    __syncthreads();
    if (n == 0) {
        float t = 0.f;
#pragma unroll
        for (int i = 0; i < 8; i++) t += sh[i];
        s_b = t;
    }
    __syncthreads();
    const float a = e / s_b + 1e-8f;
    attn[row * 256 + n] = a;
    atomicAdd(&colsum[(row >> 12) * 256 + n], a);
}

__global__ void renorm_div(float* __restrict__ attn, const float* __restrict__ colsum)
{
    const size_t row = blockIdx.x;
    const int n = threadIdx.x;
    attn[row * 256 + n] /= colsum[(row >> 12) * 256 + n];
}

// zero colsum [B*N] and upd [B*N*D] (float4 stores)
__global__ void zero_scratch(float* __restrict__ upd, float* __restrict__ cs)
{
    const size_t i = (size_t)blockIdx.x * 256 + threadIdx.x;
    ((float4*)upd)[i] = make_float4(0.f, 0.f, 0.f, 0.f);
    if (i < B_ * N_) cs[i] = 0.f;
}

// tmpl += upd / colsum[row]  (the folded L-renorm)
__global__ void apply_update(float* __restrict__ tmpl, const float* __restrict__ upd,
                             const float* __restrict__ cs)
{
    const size_t i = (size_t)blockIdx.x * 256 + threadIdx.x;
    const int row = (int)(i / (D_ / 4));
    const float s = 1.f / cs[row];
    const float4 u = ((const float4*)upd)[i];
    float4 t = ((float4*)tmpl)[i];
    t.x += u.x * s; t.y += u.y * s; t.z += u.z * s; t.w += u.w * s;
    ((float4*)tmpl)[i] = t;
}

// ---------------- tiled transpose: per batch [R,Cc] -> [Cc,R] --------------
__global__ void transpose_k(const float* __restrict__ in, float* __restrict__ out,
                            int R, int Cc)
{
    __shared__ float tile[32][33];
    const size_t base = (size_t)blockIdx.z * R * Cc;
    const int c0 = blockIdx.x * 32, r0 = blockIdx.y * 32;
#pragma unroll
    for (int i = threadIdx.y; i < 32; i += 8)
        tile[i][threadIdx.x] = in[base + (size_t)(r0 + i) * Cc + c0 + threadIdx.x];
    __syncthreads();
#pragma unroll
    for (int i = threadIdx.y; i < 32; i += 8)
        out[base + (size_t)(c0 + i) * R + r0 + threadIdx.x] = tile[threadIdx.x][i];
}

__global__ void bcast_tmpl(const float* __restrict__ tinit, float* __restrict__ tmpl)
{
    const size_t i = (size_t)blockIdx.x * 256 + threadIdx.x;
    tmpl[i] = tinit[i & ((size_t)N_ * D_ - 1)];
}

__global__ void round_copy(const float* __restrict__ in, float* __restrict__ out)
{
    const size_t i = (size_t)blockIdx.x * 256 + threadIdx.x;
    out[i] = to_tf32(in[i]);
}

// ---------------- host orchestration ---------------------------------------
extern "C" void kernel_launch(void* const* d_in, const int* in_sizes, int n_in,
                              void* d_out, int out_size)
{
    const float* x       = (const float*)d_in[0];
    const float* tinit   = (const float*)d_in[1];
    const float* Wq      = (const float*)d_in[2];
    const float* Wk      = (const float*)d_in[3];
    const float* Wv      = (const float*)d_in[4];
    const float* ln_in_g = (const float*)d_in[5];
    const float* ln_in_b = (const float*)d_in[6];
    const float* ln_t_g  = (const float*)d_in[7];
    const float* ln_t_b  = (const float*)d_in[8];
    const float* ln_m_g  = (const float*)d_in[9];
    const float* ln_m_b  = (const float*)d_in[10];
    const float* W1      = (const float*)d_in[11];
    const float* b1      = (const float*)d_in[12];
    const float* W2      = (const float*)d_in[13];
    const float* b2      = (const float*)d_in[14];
    float* out = (float*)d_out;

    float *xn, *kb, *vb, *attn, *tmpl, *tb, *qb, *mb, *hb, *upd, *cs;
    float *wq, *wk, *wv, *w1, *w2;
    cudaGetSymbolAddress((void**)&xn,   g_xn);
    cudaGetSymbolAddress((void**)&kb,   g_k);
    cudaGetSymbolAddress((void**)&vb,   g_v);
    cudaGetSymbolAddress((void**)&attn, g_attn);
    cudaGetSymbolAddress((void**)&tmpl, g_tmpl);
    cudaGetSymbolAddress((void**)&tb,   g_t);
    cudaGetSymbolAddress((void**)&qb,   g_q);
    cudaGetSymbolAddress((void**)&mb,   g_m);
    cudaGetSymbolAddress((void**)&hb,   g_h);
    cudaGetSymbolAddress((void**)&upd,  g_upd);
    cudaGetSymbolAddress((void**)&cs,   g_cs);
    cudaGetSymbolAddress((void**)&wq,   g_wq);
    cudaGetSymbolAddress((void**)&wk,   g_wk);
    cudaGetSymbolAddress((void**)&wv,   g_wv);
    cudaGetSymbolAddress((void**)&w1,   g_w1);
    cudaGetSymbolAddress((void**)&w2,   g_w2);

    // smem per instantiation: 2*(AST+BST)*4 bytes
    const int SM_KV   = 2 * (128 * 36 + 32 * 136) * 4;  // 71680  (BM128,TA0,TB0)
    const int SM_LOG  = 2 * (128 * 36 + 128 * 36) * 4;  // 73728  (BM128,TA0,TB1)
    const int SM_64NN = 2 * (64 * 36 + 32 * 136) * 4;   // 53248  (BM64, TA0,TB0)
    const int SM_UPD  = 2 * (32 * 72 + 32 * 136) * 4;   // 53248  (BM64, TA1,TB0)

    cudaFuncSetAttribute(tgemm<128,0,0,0,0,0,1,1,0>, cudaFuncAttributeMaxDynamicSharedMemorySize, SM_KV);
    cudaFuncSetAttribute(tgemm<128,0,1,0,0,0,0,1,0>, cudaFuncAttributeMaxDynamicSharedMemorySize, SM_LOG);
    cudaFuncSetAttribute(tgemm<64,0,0,0,0,0,1,1,0>,  cudaFuncAttributeMaxDynamicSharedMemorySize, SM_64NN);
    cudaFuncSetAttribute(tgemm<64,1,0,0,0,0,0,4,1>,  cudaFuncAttributeMaxDynamicSharedMemorySize, SM_UPD);
    cudaFuncSetAttribute(tgemm<64,0,0,1,1,0,1,1,0>,  cudaFuncAttributeMaxDynamicSharedMemorySize, SM_64NN);
    cudaFuncSetAttribute(tgemm<64,0,0,1,0,1,0,1,0>,  cudaFuncAttributeMaxDynamicSharedMemorySize, SM_64NN);

    const dim3 tblk(32, 8);
    const float scale = 0.03125f;  // 1024^-0.5

    // pre-round weights to tf32
    round_copy<<<(D_ * D_)   / 256, 256>>>(Wq, wq);
    round_copy<<<(C_ * D_)   / 256, 256>>>(Wk, wk);
    round_copy<<<(C_ * D_)   / 256, 256>>>(Wv, wv);
    round_copy<<<(D_ * MLP_) / 256, 256>>>(W1, w1);
    round_copy<<<(MLP_ * D_) / 256, 256>>>(W2, w2);

    // x [B,C,L] -> xn [B,L,C], then LN over C (rounded output)
    transpose_k<<<dim3(L_ / 32, C_ / 32, B_), tblk>>>(x, xn, C_, L_);
    ln1024<<<B_ * L_, 256>>>(xn, ln_in_g, ln_in_b, xn);

    // K = xn@Wk, V = xn@Wv
    tgemm<128,0,0,0,0,0,1,1,0><<<dim3(D_ / 128, (B_ * L_) / 128, 1), 128, SM_KV>>>(
        xn, wk, nullptr, nullptr, kb, B_ * L_, D_, C_, C_, D_, D_, 0, 0, 0, 1.f);
    tgemm<128,0,0,0,0,0,1,1,0><<<dim3(D_ / 128, (B_ * L_) / 128, 1), 128, SM_KV>>>(
        xn, wv, nullptr, nullptr, vb, B_ * L_, D_, C_, C_, D_, D_, 0, 0, 0, 1.f);

    bcast_tmpl<<<(B_ * N_ * D_) / 256, 256>>>(tinit, tmpl);

    for (int it = 0; it < TIT_; ++it) {
        // t = LN(t_prev); q = (t@Wq)*scale
        ln1024<<<B_ * N_, 256>>>(tmpl, ln_t_g, ln_t_b, tb);
        tgemm<64,0,0,0,0,0,1,1,0><<<dim3(D_ / 128, (B_ * N_) / 64, 1), 128, SM_64NN>>>(
            tb, wq, nullptr, nullptr, qb, B_ * N_, D_, D_, D_, D_, D_, 0, 0, 0, scale);

        // logits[b] = K[b] @ q[b]^T : [4096,256]
        tgemm<128,0,1,0,0,0,0,1,0><<<dim3(N_ / 128, L_ / 128, B_), 128, SM_LOG>>>(
            kb, qb, nullptr, nullptr, attn, L_, N_, D_, D_, D_, N_,
            (long long)L_ * D_, (long long)N_ * D_, (long long)L_ * N_, 1.f);

        // raw softmax over N (+1e-8) and per-(b,n) colsum; renorm folded below
        zero_scratch<<<(B_ * N_ * D_) / 1024, 256>>>(upd, cs);
        softmax_colsum<<<B_ * L_, 256>>>(attn, cs);

        // upd = attn_raw^T @ V via split-K x4 (atomic partials)
        tgemm<64,1,0,0,0,0,0,4,1><<<dim3(D_ / 128, N_ / 64, B_ * 4), 128, SM_UPD>>>(
            attn, vb, nullptr, nullptr, upd, N_, D_, L_, N_, D_, D_,
            (long long)L_ * N_, (long long)L_ * D_, (long long)N_ * D_, 1.f);

        // templates += upd / colsum   (exact fold of the L-renorm)
        apply_update<<<(B_ * N_ * D_) / 1024, 256>>>(tmpl, upd, cs);

        // m = LN(templates); templates += relu(m@W1+b1)@W2 + b2
        ln1024<<<B_ * N_, 256>>>(tmpl, ln_m_g, ln_m_b, mb);
        tgemm<64,0,0,1,1,0,1,1,0><<<dim3(MLP_ / 128, (B_ * N_) / 64, 1), 128, SM_64NN>>>(
            mb, w1, b1, nullptr, hb, B_ * N_, MLP_, D_, D_, MLP_, MLP_, 0, 0, 0, 1.f);
        tgemm<64,0,0,1,0,1,0,1,0><<<dim3(D_ / 128, (B_ * N_) / 64, 1), 128, SM_64NN>>>(
            hb, w2, b2, tmpl, tmpl, B_ * N_, D_, MLP_, MLP_, D_, D_, 0, 0, 0, 1.f);
    }

    // final attn renorm (only needed for the output tensor)
    renorm_div<<<B_ * L_, 256>>>(attn, cs);

    // out_templates [B,D,N]; out_attn [B,N,H,W]
    transpose_k<<<dim3(D_ / 32, N_ / 32, B_), tblk>>>(tmpl, out, N_, D_);
    transpose_k<<<dim3(N_ / 32, L_ / 32, B_), tblk>>>(
        attn, out + (size_t)B_ * D_ * N_, L_, N_);
}